// round 1
// baseline (speedup 1.0000x reference)
#include <cuda_runtime.h>
#include <cuda_bf16.h>
#include <cstdint>

// Shapes
#define BB 8
#define CC 32
#define DD 64
#define HH 64
#define WW 64
#define DP 32
#define HP 32
#define WP 32
#define HID 128
#define SEQ 16
// pooled elements per (b,c): 32*32*32 = 32768
// per (b,c,dp) plane: 32*32 = 1024

// Scratch (device globals; no allocation allowed)
__device__ float         g_pooled[BB*CC*DP*HP*WP];   // 32 MB
__device__ unsigned char g_amax  [BB*CC*DP*HP*WP];   // 8 MB
__device__ float g_psum[BB*CC*DP];   // per-(b,c,dp) plane sum
__device__ float g_psq [BB*CC*DP];   // per-(b,c,dp) plane sum of squares
__device__ float g_mod [BB*CC];
__device__ float g_A   [BB*CC];
__device__ float g_B   [BB*CC];

__inline__ __device__ float warpSum(float v) {
    #pragma unroll
    for (int o = 16; o > 0; o >>= 1) v += __shfl_down_sync(0xffffffffu, v, o);
    return v;
}

// ---------------------------------------------------------------------------
// Pass 1: maxpool 2x2x2 + argmax + per-plane sum/sumsq partials
// grid (dp=32, c=32, b=8), 256 threads, 4 pooled elems / thread
// ---------------------------------------------------------------------------
__global__ void __launch_bounds__(256) k_pool(const float* __restrict__ x) {
    const int dp = blockIdx.x, c = blockIdx.y, b = blockIdx.z;
    const int tid = threadIdx.x;
    const size_t cbase = (((size_t)b * CC + c) * DD + (size_t)(2 * dp)) * (size_t)(HH * WW);
    const int pbase = ((b * CC + c) * DP + dp) * (HP * WP);

    float lsum = 0.f, lsq = 0.f;
    #pragma unroll
    for (int j = 0; j < 4; j++) {
        const int idx = tid + 256 * j;          // 0..1023
        const int hp = idx >> 5, wp = idx & 31;
        const float* p0 = x + cbase + (size_t)(2 * hp) * WW + 2 * wp;
        const float2 v00 = *(const float2*)(p0);
        const float2 v01 = *(const float2*)(p0 + WW);
        const float2 v10 = *(const float2*)(p0 + HH * WW);
        const float2 v11 = *(const float2*)(p0 + HH * WW + WW);
        // window index = dd*4 + hh*2 + ww, first-occurrence argmax (strict >)
        float m = v00.x; int a = 0;
        if (v00.y > m) { m = v00.y; a = 1; }
        if (v01.x > m) { m = v01.x; a = 2; }
        if (v01.y > m) { m = v01.y; a = 3; }
        if (v10.x > m) { m = v10.x; a = 4; }
        if (v10.y > m) { m = v10.y; a = 5; }
        if (v11.x > m) { m = v11.x; a = 6; }
        if (v11.y > m) { m = v11.y; a = 7; }
        g_pooled[pbase + idx] = m;
        g_amax[pbase + idx] = (unsigned char)a;
        lsum += m;
        lsq  += m * m;
    }

    lsum = warpSum(lsum);
    lsq  = warpSum(lsq);
    __shared__ float ssum[8], ssq[8];
    if ((tid & 31) == 0) { ssum[tid >> 5] = lsum; ssq[tid >> 5] = lsq; }
    __syncthreads();
    if (tid == 0) {
        float s = 0.f, q = 0.f;
        #pragma unroll
        for (int w = 0; w < 8; w++) { s += ssum[w]; q += ssq[w]; }
        const int bl = (b * CC + c) * DP + dp;
        g_psum[bl] = s;
        g_psq[bl]  = q;
    }
}

// ---------------------------------------------------------------------------
// Pass 2: per-batch RNN (8 blocks, 128 threads each)
// seq[t] = mean of 2048 pooled values = (plane 2t + plane 2t+1) / 2048
// ---------------------------------------------------------------------------
__global__ void __launch_bounds__(128) k_rnn(
    const float* __restrict__ W_init, const float* __restrict__ b_init,
    const float* __restrict__ W_ih,   const float* __restrict__ b_ih,
    const float* __restrict__ W_hh,   const float* __restrict__ b_hh,
    const float* __restrict__ W_mod,  const float* __restrict__ b_mod)
{
    const int b = blockIdx.x;
    const int tid = threadIdx.x;

    __shared__ float s_seq[CC * SEQ];           // [c][t]
    __shared__ float s_pm[CC];                  // pooled mean per channel
    __shared__ __align__(16) float s_h[HID];

    if (tid < CC) {
        const int c = tid;
        const float* p = g_psum + (b * CC + c) * DP;
        float tot = 0.f;
        #pragma unroll
        for (int t = 0; t < SEQ; t++) {
            const float v = p[2 * t] + p[2 * t + 1];
            s_seq[c * SEQ + t] = v * (1.f / 2048.f);
            tot += v;
        }
        s_pm[c] = tot * (1.f / 32768.f);
    }
    __syncthreads();

    // h0 = tanh(pm @ W_init^T + b_init)
    {
        float acc = b_init[tid];
        const float* wr = W_init + tid * CC;
        #pragma unroll
        for (int c = 0; c < CC; c++) acc += s_pm[c] * wr[c];
        s_h[tid] = tanhf(acc);
    }
    __syncthreads();

    const float bias = b_ih[tid] + b_hh[tid];
    const float4* whr = (const float4*)(W_hh + tid * HID);
    const float4* wir = (const float4*)(W_ih + tid * CC);

    for (int t = 0; t < SEQ; t++) {
        float acc = bias;
        // input contribution
        #pragma unroll
        for (int q = 0; q < CC / 4; q++) {
            const float4 w = wir[q];
            acc += w.x * s_seq[(q * 4 + 0) * SEQ + t];
            acc += w.y * s_seq[(q * 4 + 1) * SEQ + t];
            acc += w.z * s_seq[(q * 4 + 2) * SEQ + t];
            acc += w.w * s_seq[(q * 4 + 3) * SEQ + t];
        }
        // recurrent contribution
        const float4* hr = (const float4*)s_h;
        #pragma unroll 8
        for (int k = 0; k < HID / 4; k++) {
            const float4 w = whr[k];
            const float4 h = hr[k];
            acc += w.x * h.x + w.y * h.y + w.z * h.z + w.w * h.w;
        }
        const float hn = tanhf(acc);
        __syncthreads();          // all reads of s_h done
        s_h[tid] = hn;
        __syncthreads();          // all writes visible
    }

    if (tid < CC) {
        float acc = b_mod[tid];
        const float4* wr = (const float4*)(W_mod + tid * HID);
        const float4* hr = (const float4*)s_h;
        #pragma unroll 8
        for (int k = 0; k < HID / 4; k++) {
            const float4 w = wr[k];
            const float4 h = hr[k];
            acc += w.x * h.x + w.y * h.y + w.z * h.z + w.w * h.w;
        }
        g_mod[b * CC + tid] = 1.f / (1.f + __expf(-acc));
    }
}

// ---------------------------------------------------------------------------
// Pass 2b: channel batch-stats + fold BN + modulation into affine (A, B)
// pm = pooled * A[b,c] + B[b,c]
// ---------------------------------------------------------------------------
__global__ void __launch_bounds__(256) k_stats(
    const float* __restrict__ gamma, const float* __restrict__ beta)
{
    __shared__ float s_mean[CC], s_rstd[CC];
    const int tid = threadIdx.x;
    if (tid < CC) {
        const int c = tid;
        float s = 0.f, q = 0.f;
        for (int b = 0; b < BB; b++) {
            const float* p  = g_psum + (b * CC + c) * DP;
            const float* p2 = g_psq  + (b * CC + c) * DP;
            #pragma unroll
            for (int dp = 0; dp < DP; dp++) { s += p[dp]; q += p2[dp]; }
        }
        const float inv_n = 1.f / (float)(BB * DP * HP * WP);   // 1/262144
        const float mean = s * inv_n;
        const float var  = q * inv_n - mean * mean;             // biased var
        s_mean[c] = mean;
        s_rstd[c] = rsqrtf(var + 1e-5f);
    }
    __syncthreads();
    // tid = b*32 + c
    const int c = tid & 31;
    const float g = gamma[c] * s_rstd[c];
    const float f = 0.5f + g_mod[tid];        // 1 + (mod - 0.5)
    g_A[tid] = g * f;
    g_B[tid] = (beta[c] - s_mean[c] * g) * f;
}

// ---------------------------------------------------------------------------
// Pass 3: unpool-scatter. Writes every output element (zeros + one value
// per 2x2x2 window). Fully coalesced float2 stores.
// ---------------------------------------------------------------------------
__global__ void __launch_bounds__(256) k_scatter(float* __restrict__ out) {
    const int dp = blockIdx.x, c = blockIdx.y, b = blockIdx.z;
    const int tid = threadIdx.x;
    const float A  = g_A[b * CC + c];
    const float Bv = g_B[b * CC + c];
    const int pbase = ((b * CC + c) * DP + dp) * (HP * WP);
    const size_t obase = (((size_t)b * CC + c) * DD + (size_t)(2 * dp)) * (size_t)(HH * WW);

    #pragma unroll
    for (int j = 0; j < 4; j++) {
        const int idx = tid + 256 * j;
        const int hp = idx >> 5, wp = idx & 31;
        const float pm = g_pooled[pbase + idx] * A + Bv;
        const int a = (int)g_amax[pbase + idx];
        float* p0 = out + obase + (size_t)(2 * hp) * WW + 2 * wp;
        float2 z0, z1, z2, z3;
        z0.x = (a == 0) ? pm : 0.f;  z0.y = (a == 1) ? pm : 0.f;
        z1.x = (a == 2) ? pm : 0.f;  z1.y = (a == 3) ? pm : 0.f;
        z2.x = (a == 4) ? pm : 0.f;  z2.y = (a == 5) ? pm : 0.f;
        z3.x = (a == 6) ? pm : 0.f;  z3.y = (a == 7) ? pm : 0.f;
        *(float2*)(p0)                = z0;
        *(float2*)(p0 + WW)           = z1;
        *(float2*)(p0 + HH * WW)      = z2;
        *(float2*)(p0 + HH * WW + WW) = z3;
    }
}

// ---------------------------------------------------------------------------
// Launch
// Inputs (metadata order): x, W_init, b_init, W_ih, b_ih, W_hh, b_hh,
//                          W_mod, b_mod, gamma, beta
// ---------------------------------------------------------------------------
extern "C" void kernel_launch(void* const* d_in, const int* in_sizes, int n_in,
                              void* d_out, int out_size) {
    const float* x      = (const float*)d_in[0];
    const float* W_init = (const float*)d_in[1];
    const float* b_init = (const float*)d_in[2];
    const float* W_ih   = (const float*)d_in[3];
    const float* b_ih   = (const float*)d_in[4];
    const float* W_hh   = (const float*)d_in[5];
    const float* b_hh   = (const float*)d_in[6];
    const float* W_mod  = (const float*)d_in[7];
    const float* b_mod  = (const float*)d_in[8];
    const float* gamma  = (const float*)d_in[9];
    const float* beta   = (const float*)d_in[10];
    float* out = (float*)d_out;

    dim3 grid(DP, CC, BB);
    k_pool<<<grid, 256>>>(x);
    k_rnn<<<BB, HID>>>(W_init, b_init, W_ih, b_ih, W_hh, b_hh, W_mod, b_mod);
    k_stats<<<1, 256>>>(gamma, beta);
    k_scatter<<<grid, 256>>>(out);
}

// round 2
// speedup vs baseline: 1.2358x; 1.2358x over previous
#include <cuda_runtime.h>
#include <cuda_bf16.h>
#include <cstdint>

// Shapes
#define BB 8
#define CC 32
#define DD 64
#define HH 64
#define WW 64
#define DP 32
#define HP 32
#define WP 32
#define HID 128
#define SEQ 16
#define HW (HH*WW)

// Scratch (device globals; no allocation allowed)
__device__ float         g_pooled[BB*CC*DP*HP*WP];   // 32 MB
__device__ unsigned char g_amax  [BB*CC*DP*HP*WP];   // 8 MB
__device__ float g_psum[BB*CC*DP];   // per-(b,c,dp) plane sum
__device__ float g_psq [BB*CC*DP];   // per-(b,c,dp) plane sum of squares
__device__ float g_mod [BB*CC];
__device__ float g_mean[CC];         // channel mean
__device__ float g_g   [CC];         // gamma * rstd

__inline__ __device__ float warpSum(float v) {
    #pragma unroll
    for (int o = 16; o > 0; o >>= 1) v += __shfl_down_sync(0xffffffffu, v, o);
    return v;
}

// window-local compare chain: first-occurrence argmax (strict >)
__inline__ __device__ void wmax(float v, int i, float& m, int& a) {
    if (v > m) { m = v; a = i; }
}

// ---------------------------------------------------------------------------
// Pass 1: maxpool 2x2x2 + argmax + per-plane sum/sumsq partials
// grid (dp=32, c=32, b=8), 256 threads, 4 windows / thread, all float4.
// tid -> hp = tid>>3 (0..31), q = tid&7; windows (hp, 4q..4q+3)
// ---------------------------------------------------------------------------
__global__ void __launch_bounds__(256) k_pool(const float* __restrict__ x) {
    const int dp = blockIdx.x, c = blockIdx.y, b = blockIdx.z;
    const int tid = threadIdx.x;
    const int hp = tid >> 3, q = tid & 7;
    const size_t cbase = (((size_t)b * CC + c) * DD + (size_t)(2 * dp)) * (size_t)HW;
    const int pbase = ((b * CC + c) * DP + dp) * (HP * WP);

    const float* r00 = x + cbase + (size_t)(2 * hp) * WW + 8 * q;
    const float4 a0 = __ldcs((const float4*)(r00));
    const float4 a1 = __ldcs((const float4*)(r00 + 4));
    const float4 b0 = __ldcs((const float4*)(r00 + WW));
    const float4 b1 = __ldcs((const float4*)(r00 + WW + 4));
    const float4 c0 = __ldcs((const float4*)(r00 + HW));
    const float4 c1 = __ldcs((const float4*)(r00 + HW + 4));
    const float4 d0 = __ldcs((const float4*)(r00 + HW + WW));
    const float4 d1 = __ldcs((const float4*)(r00 + HW + WW + 4));

    float m0 = a0.x; int i0 = 0;
    wmax(a0.y,1,m0,i0); wmax(b0.x,2,m0,i0); wmax(b0.y,3,m0,i0);
    wmax(c0.x,4,m0,i0); wmax(c0.y,5,m0,i0); wmax(d0.x,6,m0,i0); wmax(d0.y,7,m0,i0);
    float m1 = a0.z; int i1 = 0;
    wmax(a0.w,1,m1,i1); wmax(b0.z,2,m1,i1); wmax(b0.w,3,m1,i1);
    wmax(c0.z,4,m1,i1); wmax(c0.w,5,m1,i1); wmax(d0.z,6,m1,i1); wmax(d0.w,7,m1,i1);
    float m2 = a1.x; int i2 = 0;
    wmax(a1.y,1,m2,i2); wmax(b1.x,2,m2,i2); wmax(b1.y,3,m2,i2);
    wmax(c1.x,4,m2,i2); wmax(c1.y,5,m2,i2); wmax(d1.x,6,m2,i2); wmax(d1.y,7,m2,i2);
    float m3 = a1.z; int i3 = 0;
    wmax(a1.w,1,m3,i3); wmax(b1.z,2,m3,i3); wmax(b1.w,3,m3,i3);
    wmax(c1.z,4,m3,i3); wmax(c1.w,5,m3,i3); wmax(d1.z,6,m3,i3); wmax(d1.w,7,m3,i3);

    const int pidx = pbase + hp * 32 + 4 * q;
    *(float4*)(g_pooled + pidx) = make_float4(m0, m1, m2, m3);
    uchar4 am; am.x = (unsigned char)i0; am.y = (unsigned char)i1;
              am.z = (unsigned char)i2; am.w = (unsigned char)i3;
    *(uchar4*)(g_amax + pidx) = am;

    float lsum = m0 + m1 + m2 + m3;
    float lsq  = m0*m0 + m1*m1 + m2*m2 + m3*m3;
    lsum = warpSum(lsum);
    lsq  = warpSum(lsq);
    __shared__ float ssum[8], ssq[8];
    if ((tid & 31) == 0) { ssum[tid >> 5] = lsum; ssq[tid >> 5] = lsq; }
    __syncthreads();
    if (tid == 0) {
        float s = 0.f, qq = 0.f;
        #pragma unroll
        for (int w = 0; w < 8; w++) { s += ssum[w]; qq += ssq[w]; }
        const int bl = (b * CC + c) * DP + dp;
        g_psum[bl] = s;
        g_psq[bl]  = qq;
    }
}

// ---------------------------------------------------------------------------
// Pass 2: per-batch RNN (blocks 0..7) + channel stats (block 8)
// ---------------------------------------------------------------------------
__global__ void __launch_bounds__(128) k_rnn(
    const float* __restrict__ W_init, const float* __restrict__ b_init,
    const float* __restrict__ W_ih,   const float* __restrict__ b_ih,
    const float* __restrict__ W_hh,   const float* __restrict__ b_hh,
    const float* __restrict__ W_mod,  const float* __restrict__ b_mod,
    const float* __restrict__ gamma)
{
    const int blk = blockIdx.x;
    const int tid = threadIdx.x;

    if (blk == 8) {
        // channel stats: c = tid&31, 2 batches per thread part = tid>>5
        __shared__ float sh_s[4][CC], sh_q[4][CC];
        const int c = tid & 31, part = tid >> 5;
        float s = 0.f, qv = 0.f;
        #pragma unroll
        for (int bi = 0; bi < 2; bi++) {
            const int b = part * 2 + bi;
            const float* p  = g_psum + (b * CC + c) * DP;
            const float* p2 = g_psq  + (b * CC + c) * DP;
            #pragma unroll
            for (int dp = 0; dp < DP; dp++) { s += p[dp]; qv += p2[dp]; }
        }
        sh_s[part][c] = s; sh_q[part][c] = qv;
        __syncthreads();
        if (tid < CC) {
            float ts = 0.f, tq = 0.f;
            #pragma unroll
            for (int p = 0; p < 4; p++) { ts += sh_s[p][tid]; tq += sh_q[p][tid]; }
            const float inv_n = 1.f / (float)(BB * DP * HP * WP);
            const float mean = ts * inv_n;
            const float var  = tq * inv_n - mean * mean;
            g_mean[tid] = mean;
            g_g[tid]    = gamma[tid] * rsqrtf(var + 1e-5f);
        }
        return;
    }

    const int b = blk;
    __shared__ float s_seq[CC * SEQ];               // [c][t]
    __shared__ float s_pm[CC];
    __shared__ __align__(16) float s_h[2][HID];

    if (tid < CC) {
        const int c = tid;
        const float* p = g_psum + (b * CC + c) * DP;
        float tot = 0.f;
        #pragma unroll
        for (int t = 0; t < SEQ; t++) {
            const float v = p[2 * t] + p[2 * t + 1];
            s_seq[c * SEQ + t] = v * (1.f / 2048.f);
            tot += v;
        }
        s_pm[c] = tot * (1.f / 32768.f);
    }
    __syncthreads();

    // h0
    {
        float acc = b_init[tid];
        const float* wr = W_init + tid * CC;
        #pragma unroll
        for (int c = 0; c < CC; c++) acc += s_pm[c] * wr[c];
        s_h[0][tid] = tanhf(acc);
    }

    // precompute u[t] = W_ih@seq_t + b_ih + b_hh
    const float bias = b_ih[tid] + b_hh[tid];
    float u[SEQ];
    {
        const float4* wir = (const float4*)(W_ih + tid * CC);
        float4 wi[CC/4];
        #pragma unroll
        for (int qk = 0; qk < CC/4; qk++) wi[qk] = wir[qk];
        #pragma unroll
        for (int t = 0; t < SEQ; t++) {
            float acc = bias;
            #pragma unroll
            for (int qk = 0; qk < CC/4; qk++) {
                acc += wi[qk].x * s_seq[(qk*4+0)*SEQ + t];
                acc += wi[qk].y * s_seq[(qk*4+1)*SEQ + t];
                acc += wi[qk].z * s_seq[(qk*4+2)*SEQ + t];
                acc += wi[qk].w * s_seq[(qk*4+3)*SEQ + t];
            }
            u[t] = acc;
        }
    }

    // preload W_hh row into registers (32 x float4)
    float4 wreg[HID/4];
    {
        const float4* whr = (const float4*)(W_hh + tid * HID);
        #pragma unroll
        for (int k = 0; k < HID/4; k++) wreg[k] = whr[k];
    }
    __syncthreads();   // s_h[0] ready

    #pragma unroll
    for (int t = 0; t < SEQ; t++) {
        const int cur = t & 1;
        float acc = u[t];
        const float4* hr = (const float4*)s_h[cur];
        #pragma unroll
        for (int k = 0; k < HID/4; k++) {
            const float4 w = wreg[k];
            const float4 h = hr[k];
            acc += w.x*h.x + w.y*h.y + w.z*h.z + w.w*h.w;
        }
        s_h[cur ^ 1][tid] = tanhf(acc);
        __syncthreads();
    }

    if (tid < CC) {
        float acc = b_mod[tid];
        const float4* wr = (const float4*)(W_mod + tid * HID);
        const float4* hr = (const float4*)s_h[SEQ & 1];
        #pragma unroll
        for (int k = 0; k < HID/4; k++) {
            const float4 w = wr[k];
            const float4 h = hr[k];
            acc += w.x*h.x + w.y*h.y + w.z*h.z + w.w*h.w;
        }
        g_mod[b * CC + tid] = 1.f / (1.f + __expf(-acc));
    }
}

// ---------------------------------------------------------------------------
// Pass 3: unpool-scatter with inline BN/modulation fold. float4 stores.
// Same thread->window layout as k_pool.
// ---------------------------------------------------------------------------
__global__ void __launch_bounds__(256) k_scatter(float* __restrict__ out,
                                                 const float* __restrict__ beta) {
    const int dp = blockIdx.x, c = blockIdx.y, b = blockIdx.z;
    const int tid = threadIdx.x;
    const int hp = tid >> 3, q = tid & 7;

    const float f = 0.5f + g_mod[b * CC + c];   // 1 + (mod - 0.5)
    const float g = g_g[c];
    const float A  = g * f;
    const float Bv = (beta[c] - g_mean[c] * g) * f;

    const int pidx = ((b * CC + c) * DP + dp) * (HP * WP) + hp * 32 + 4 * q;
    const float4 pm4 = *(const float4*)(g_pooled + pidx);
    const uchar4 am  = *(const uchar4*)(g_amax + pidx);

    const float p0 = pm4.x * A + Bv;
    const float p1 = pm4.y * A + Bv;
    const float p2 = pm4.z * A + Bv;
    const float p3 = pm4.w * A + Bv;
    const int a0 = am.x, a1 = am.y, a2 = am.z, a3 = am.w;

    const size_t obase = (((size_t)b * CC + c) * DD + (size_t)(2 * dp)) * (size_t)HW
                       + (size_t)(2 * hp) * WW + 8 * q;
    float* r00 = out + obase;

    // row (dd,hh): windows 0,1 -> first float4; windows 2,3 -> second float4
    float4 v;
    // dd=0, hh=0 (local idx 0,1)
    v = make_float4(a0==0?p0:0.f, a0==1?p0:0.f, a1==0?p1:0.f, a1==1?p1:0.f);
    *(float4*)(r00) = v;
    v = make_float4(a2==0?p2:0.f, a2==1?p2:0.f, a3==0?p3:0.f, a3==1?p3:0.f);
    *(float4*)(r00 + 4) = v;
    // dd=0, hh=1 (local idx 2,3)
    v = make_float4(a0==2?p0:0.f, a0==3?p0:0.f, a1==2?p1:0.f, a1==3?p1:0.f);
    *(float4*)(r00 + WW) = v;
    v = make_float4(a2==2?p2:0.f, a2==3?p2:0.f, a3==2?p3:0.f, a3==3?p3:0.f);
    *(float4*)(r00 + WW + 4) = v;
    // dd=1, hh=0 (local idx 4,5)
    v = make_float4(a0==4?p0:0.f, a0==5?p0:0.f, a1==4?p1:0.f, a1==5?p1:0.f);
    *(float4*)(r00 + HW) = v;
    v = make_float4(a2==4?p2:0.f, a2==5?p2:0.f, a3==4?p3:0.f, a3==5?p3:0.f);
    *(float4*)(r00 + HW + 4) = v;
    // dd=1, hh=1 (local idx 6,7)
    v = make_float4(a0==6?p0:0.f, a0==7?p0:0.f, a1==6?p1:0.f, a1==7?p1:0.f);
    *(float4*)(r00 + HW + WW) = v;
    v = make_float4(a2==6?p2:0.f, a2==7?p2:0.f, a3==6?p3:0.f, a3==7?p3:0.f);
    *(float4*)(r00 + HW + WW + 4) = v;
}

// ---------------------------------------------------------------------------
// Launch
// Inputs: x, W_init, b_init, W_ih, b_ih, W_hh, b_hh, W_mod, b_mod, gamma, beta
// ---------------------------------------------------------------------------
extern "C" void kernel_launch(void* const* d_in, const int* in_sizes, int n_in,
                              void* d_out, int out_size) {
    const float* x      = (const float*)d_in[0];
    const float* W_init = (const float*)d_in[1];
    const float* b_init = (const float*)d_in[2];
    const float* W_ih   = (const float*)d_in[3];
    const float* b_ih   = (const float*)d_in[4];
    const float* W_hh   = (const float*)d_in[5];
    const float* b_hh   = (const float*)d_in[6];
    const float* W_mod  = (const float*)d_in[7];
    const float* b_mod  = (const float*)d_in[8];
    const float* gamma  = (const float*)d_in[9];
    const float* beta   = (const float*)d_in[10];
    float* out = (float*)d_out;

    dim3 grid(DP, CC, BB);
    k_pool<<<grid, 256>>>(x);
    k_rnn<<<9, 128>>>(W_init, b_init, W_ih, b_ih, W_hh, b_hh, W_mod, b_mod, gamma);
    k_scatter<<<grid, 256>>>(out, beta);
}

// round 3
// speedup vs baseline: 1.2821x; 1.0374x over previous
#include <cuda_runtime.h>
#include <cuda_bf16.h>
#include <cstdint>

// Shapes
#define BB 8
#define CC 32
#define DD 64
#define HH 64
#define WW 64
#define DP 32
#define HP 32
#define WP 32
#define HID 128
#define SEQ 16
#define HW (HH*WW)

// Scratch (device globals; no allocation allowed)
__device__ float         g_pooled[BB*CC*DP*HP*WP];   // 32 MB
__device__ unsigned char g_amax  [BB*CC*DP*HP*WP];   // 8 MB
__device__ float g_psum[BB*CC*DP];   // per-(b,c,dp) plane sum
__device__ float g_psq [BB*CC*DP];   // per-(b,c,dp) plane sum of squares
__device__ float g_mod [BB*CC];
__device__ float g_mean[CC];         // channel mean
__device__ float g_g   [CC];         // gamma * rstd

__inline__ __device__ float warpSum(float v) {
    #pragma unroll
    for (int o = 16; o > 0; o >>= 1) v += __shfl_down_sync(0xffffffffu, v, o);
    return v;
}

__inline__ __device__ void wmax(float v, int i, float& m, int& a) {
    if (v > m) { m = v; a = i; }
}

// ---------------------------------------------------------------------------
// Pass 1: maxpool 2x2x2 + argmax + per-plane sum/sumsq partials
// grid (dp=32, c=32, b=8), 256 threads, 4 windows / thread, all float4.
// ---------------------------------------------------------------------------
__global__ void __launch_bounds__(256) k_pool(const float* __restrict__ x) {
    const int dp = blockIdx.x, c = blockIdx.y, b = blockIdx.z;
    const int tid = threadIdx.x;
    const int hp = tid >> 3, q = tid & 7;
    const size_t cbase = (((size_t)b * CC + c) * DD + (size_t)(2 * dp)) * (size_t)HW;
    const int pbase = ((b * CC + c) * DP + dp) * (HP * WP);

    const float* r00 = x + cbase + (size_t)(2 * hp) * WW + 8 * q;
    const float4 a0 = __ldcs((const float4*)(r00));
    const float4 a1 = __ldcs((const float4*)(r00 + 4));
    const float4 b0 = __ldcs((const float4*)(r00 + WW));
    const float4 b1 = __ldcs((const float4*)(r00 + WW + 4));
    const float4 c0 = __ldcs((const float4*)(r00 + HW));
    const float4 c1 = __ldcs((const float4*)(r00 + HW + 4));
    const float4 d0 = __ldcs((const float4*)(r00 + HW + WW));
    const float4 d1 = __ldcs((const float4*)(r00 + HW + WW + 4));

    float m0 = a0.x; int i0 = 0;
    wmax(a0.y,1,m0,i0); wmax(b0.x,2,m0,i0); wmax(b0.y,3,m0,i0);
    wmax(c0.x,4,m0,i0); wmax(c0.y,5,m0,i0); wmax(d0.x,6,m0,i0); wmax(d0.y,7,m0,i0);
    float m1 = a0.z; int i1 = 0;
    wmax(a0.w,1,m1,i1); wmax(b0.z,2,m1,i1); wmax(b0.w,3,m1,i1);
    wmax(c0.z,4,m1,i1); wmax(c0.w,5,m1,i1); wmax(d0.z,6,m1,i1); wmax(d0.w,7,m1,i1);
    float m2 = a1.x; int i2 = 0;
    wmax(a1.y,1,m2,i2); wmax(b1.x,2,m2,i2); wmax(b1.y,3,m2,i2);
    wmax(c1.x,4,m2,i2); wmax(c1.y,5,m2,i2); wmax(d1.x,6,m2,i2); wmax(d1.y,7,m2,i2);
    float m3 = a1.z; int i3 = 0;
    wmax(a1.w,1,m3,i3); wmax(b1.z,2,m3,i3); wmax(b1.w,3,m3,i3);
    wmax(c1.z,4,m3,i3); wmax(c1.w,5,m3,i3); wmax(d1.z,6,m3,i3); wmax(d1.w,7,m3,i3);

    const int pidx = pbase + hp * 32 + 4 * q;
    *(float4*)(g_pooled + pidx) = make_float4(m0, m1, m2, m3);
    uchar4 am; am.x = (unsigned char)i0; am.y = (unsigned char)i1;
              am.z = (unsigned char)i2; am.w = (unsigned char)i3;
    *(uchar4*)(g_amax + pidx) = am;

    float lsum = m0 + m1 + m2 + m3;
    float lsq  = m0*m0 + m1*m1 + m2*m2 + m3*m3;
    lsum = warpSum(lsum);
    lsq  = warpSum(lsq);
    __shared__ float ssum[8], ssq[8];
    if ((tid & 31) == 0) { ssum[tid >> 5] = lsum; ssq[tid >> 5] = lsq; }
    __syncthreads();
    if (tid == 0) {
        float s = 0.f, qq = 0.f;
        #pragma unroll
        for (int w = 0; w < 8; w++) { s += ssum[w]; qq += ssq[w]; }
        const int bl = (b * CC + c) * DP + dp;
        g_psum[bl] = s;
        g_psq[bl]  = qq;
    }
}

// ---------------------------------------------------------------------------
// Pass 2: per-batch RNN (blocks 0..7) + channel stats (block 8)
// Register budget: only W_hh row lives in regs (128) — everything else in smem.
// ---------------------------------------------------------------------------
__global__ void __launch_bounds__(128, 1) k_rnn(
    const float* __restrict__ W_init, const float* __restrict__ b_init,
    const float* __restrict__ W_ih,   const float* __restrict__ b_ih,
    const float* __restrict__ W_hh,   const float* __restrict__ b_hh,
    const float* __restrict__ W_mod,  const float* __restrict__ b_mod,
    const float* __restrict__ gamma)
{
    const int blk = blockIdx.x;
    const int tid = threadIdx.x;

    if (blk == 8) {
        __shared__ float sh_s[4][CC], sh_q[4][CC];
        const int c = tid & 31, part = tid >> 5;
        float s = 0.f, qv = 0.f;
        #pragma unroll
        for (int bi = 0; bi < 2; bi++) {
            const int b = part * 2 + bi;
            const float* p  = g_psum + (b * CC + c) * DP;
            const float* p2 = g_psq  + (b * CC + c) * DP;
            #pragma unroll
            for (int dp = 0; dp < DP; dp++) { s += p[dp]; qv += p2[dp]; }
        }
        sh_s[part][c] = s; sh_q[part][c] = qv;
        __syncthreads();
        if (tid < CC) {
            float ts = 0.f, tq = 0.f;
            #pragma unroll
            for (int p = 0; p < 4; p++) { ts += sh_s[p][tid]; tq += sh_q[p][tid]; }
            const float inv_n = 1.f / (float)(BB * DP * HP * WP);
            const float mean = ts * inv_n;
            const float var  = tq * inv_n - mean * mean;
            g_mean[tid] = mean;
            g_g[tid]    = gamma[tid] * rsqrtf(var + 1e-5f);
        }
        return;
    }

    const int b = blk;
    __shared__ float s_seq[CC * SEQ];               // [c][t]
    __shared__ float s_pm[CC];
    __shared__ float s_u[SEQ * HID];                // precomputed input projections
    __shared__ __align__(16) float s_h[2][HID];

    if (tid < CC) {
        const int c = tid;
        const float* p = g_psum + (b * CC + c) * DP;
        float tot = 0.f;
        #pragma unroll
        for (int t = 0; t < SEQ; t++) {
            const float v = p[2 * t] + p[2 * t + 1];
            s_seq[c * SEQ + t] = v * (1.f / 2048.f);
            tot += v;
        }
        s_pm[c] = tot * (1.f / 32768.f);
    }
    __syncthreads();

    // h0 = tanh(pm @ W_init^T + b_init)
    {
        float acc = b_init[tid];
        const float* wr = W_init + tid * CC;
        #pragma unroll
        for (int c = 0; c < CC; c++) acc += s_pm[c] * wr[c];
        s_h[0][tid] = tanhf(acc);
    }

    // u[t] = W_ih@seq_t + b_ih + b_hh  -> shared (no register arrays kept live)
    {
        const float bias = b_ih[tid] + b_hh[tid];
        const float4* wir = (const float4*)(W_ih + tid * CC);
        for (int t = 0; t < SEQ; t++) {
            float acc = bias;
            #pragma unroll
            for (int qk = 0; qk < CC/4; qk++) {
                const float4 w = wir[qk];      // L1-warm after t=0
                acc += w.x * s_seq[(qk*4+0)*SEQ + t];
                acc += w.y * s_seq[(qk*4+1)*SEQ + t];
                acc += w.z * s_seq[(qk*4+2)*SEQ + t];
                acc += w.w * s_seq[(qk*4+3)*SEQ + t];
            }
            s_u[t * HID + tid] = acc;
        }
    }

    // W_hh row -> registers (the only big register array)
    float4 wreg[HID/4];
    {
        const float4* whr = (const float4*)(W_hh + tid * HID);
        #pragma unroll
        for (int k = 0; k < HID/4; k++) wreg[k] = whr[k];
    }
    __syncthreads();

    #pragma unroll 1
    for (int t = 0; t < SEQ; t++) {
        const int cur = t & 1;
        float acc = s_u[t * HID + tid];
        const float4* hr = (const float4*)s_h[cur];
        #pragma unroll
        for (int k = 0; k < HID/4; k++) {
            const float4 w = wreg[k];
            const float4 h = hr[k];
            acc += w.x*h.x + w.y*h.y + w.z*h.z + w.w*h.w;
        }
        s_h[cur ^ 1][tid] = tanhf(acc);
        __syncthreads();
    }

    if (tid < CC) {
        float acc = b_mod[tid];
        const float4* wr = (const float4*)(W_mod + tid * HID);
        const float4* hr = (const float4*)s_h[SEQ & 1];
        #pragma unroll
        for (int k = 0; k < HID/4; k++) {
            const float4 w = wr[k];
            const float4 h = hr[k];
            acc += w.x*h.x + w.y*h.y + w.z*h.z + w.w*h.w;
        }
        g_mod[b * CC + tid] = 1.f / (1.f + __expf(-acc));
    }
}

// ---------------------------------------------------------------------------
// Pass 3: unpool-scatter, BN/mod folded. Streaming stores (__stcs) keep the
// pooled/amax lines (written by k_pool, still L2-resident) from being evicted.
// ---------------------------------------------------------------------------
__global__ void __launch_bounds__(256) k_scatter(float* __restrict__ out,
                                                 const float* __restrict__ beta) {
    const int dp = blockIdx.x, c = blockIdx.y, b = blockIdx.z;
    const int tid = threadIdx.x;
    const int hp = tid >> 3, q = tid & 7;

    const float f = 0.5f + g_mod[b * CC + c];   // 1 + (mod - 0.5)
    const float g = g_g[c];
    const float A  = g * f;
    const float Bv = (beta[c] - g_mean[c] * g) * f;

    const int pidx = ((b * CC + c) * DP + dp) * (HP * WP) + hp * 32 + 4 * q;
    const float4 pm4 = *(const float4*)(g_pooled + pidx);
    const uchar4 am  = *(const uchar4*)(g_amax + pidx);

    const float p0 = pm4.x * A + Bv;
    const float p1 = pm4.y * A + Bv;
    const float p2 = pm4.z * A + Bv;
    const float p3 = pm4.w * A + Bv;
    const int a0 = am.x, a1 = am.y, a2 = am.z, a3 = am.w;

    const size_t obase = (((size_t)b * CC + c) * DD + (size_t)(2 * dp)) * (size_t)HW
                       + (size_t)(2 * hp) * WW + 8 * q;
    float* r00 = out + obase;

    float4 v;
    v = make_float4(a0==0?p0:0.f, a0==1?p0:0.f, a1==0?p1:0.f, a1==1?p1:0.f);
    __stcs((float4*)(r00), v);
    v = make_float4(a2==0?p2:0.f, a2==1?p2:0.f, a3==0?p3:0.f, a3==1?p3:0.f);
    __stcs((float4*)(r00 + 4), v);
    v = make_float4(a0==2?p0:0.f, a0==3?p0:0.f, a1==2?p1:0.f, a1==3?p1:0.f);
    __stcs((float4*)(r00 + WW), v);
    v = make_float4(a2==2?p2:0.f, a2==3?p2:0.f, a3==2?p3:0.f, a3==3?p3:0.f);
    __stcs((float4*)(r00 + WW + 4), v);
    v = make_float4(a0==4?p0:0.f, a0==5?p0:0.f, a1==4?p1:0.f, a1==5?p1:0.f);
    __stcs((float4*)(r00 + HW), v);
    v = make_float4(a2==4?p2:0.f, a2==5?p2:0.f, a3==4?p3:0.f, a3==5?p3:0.f);
    __stcs((float4*)(r00 + HW + 4), v);
    v = make_float4(a0==6?p0:0.f, a0==7?p0:0.f, a1==6?p1:0.f, a1==7?p1:0.f);
    __stcs((float4*)(r00 + HW + WW), v);
    v = make_float4(a2==6?p2:0.f, a2==7?p2:0.f, a3==6?p3:0.f, a3==7?p3:0.f);
    __stcs((float4*)(r00 + HW + WW + 4), v);
}

// ---------------------------------------------------------------------------
// Launch
// Inputs: x, W_init, b_init, W_ih, b_ih, W_hh, b_hh, W_mod, b_mod, gamma, beta
// ---------------------------------------------------------------------------
extern "C" void kernel_launch(void* const* d_in, const int* in_sizes, int n_in,
                              void* d_out, int out_size) {
    const float* x      = (const float*)d_in[0];
    const float* W_init = (const float*)d_in[1];
    const float* b_init = (const float*)d_in[2];
    const float* W_ih   = (const float*)d_in[3];
    const float* b_ih   = (const float*)d_in[4];
    const float* W_hh   = (const float*)d_in[5];
    const float* b_hh   = (const float*)d_in[6];
    const float* W_mod  = (const float*)d_in[7];
    const float* b_mod  = (const float*)d_in[8];
    const float* gamma  = (const float*)d_in[9];
    const float* beta   = (const float*)d_in[10];
    float* out = (float*)d_out;

    dim3 grid(DP, CC, BB);
    k_pool<<<grid, 256>>>(x);
    k_rnn<<<9, 128>>>(W_init, b_init, W_ih, b_ih, W_hh, b_hh, W_mod, b_mod, gamma);
    k_scatter<<<grid, 256>>>(out, beta);
}